// round 1
// baseline (speedup 1.0000x reference)
#include <cuda_runtime.h>

#define N_NODES   20000
#define N_EDGES   160000
#define N_GRAPHS  64
#define IN_DIM    128
#define HID       512
#define N_CLASSES 16

// ---------------- scratch (static device globals; no allocation) ----------------
__device__ float g_bufA[N_NODES * HID];   // GEMM output / scatter source
__device__ float g_bufB[N_NODES * HID];   // scatter target / layer activations
__device__ float g_dout[N_NODES];         // rsqrt(out-degree)
__device__ float g_din [N_NODES];         // rsqrt(in-degree)
__device__ float g_pool[N_GRAPHS * HID];
__device__ float g_cnt [N_GRAPHS];
__device__ float g_mlp1[N_GRAPHS * HID];
__device__ float g_mlp2[N_GRAPHS * HID];

// ---------------- utility kernels ----------------
__global__ void zero_f(float* p, int n) {
    int i = blockIdx.x * blockDim.x + threadIdx.x;
    if (i < n) p[i] = 0.0f;
}

__global__ void zero_f4(float* p, int n4) {   // n4 = count/4
    int i = blockIdx.x * blockDim.x + threadIdx.x;
    if (i < n4) reinterpret_cast<float4*>(p)[i] = make_float4(0.f, 0.f, 0.f, 0.f);
}

__global__ void deg_kernel(const int* __restrict__ src, const int* __restrict__ dst,
                           float* dout, float* din) {
    int e = blockIdx.x * blockDim.x + threadIdx.x;
    if (e < N_EDGES) {
        atomicAdd(&dout[src[e]], 1.0f);
        atomicAdd(&din [dst[e]], 1.0f);
    }
}

__global__ void isqrt_kernel(float* dout, float* din) {
    int i = blockIdx.x * blockDim.x + threadIdx.x;
    if (i < N_NODES) {
        dout[i] = rsqrtf(fmaxf(dout[i], 1.0f));
        din [i] = rsqrtf(fmaxf(din [i], 1.0f));
    }
}

// ---------------- fused row-scaled GEMM: C[M,512] = (rowScale[i]*A[i,:]) @ W[K,512] ----------------
// Block tile 128x64, BK=16, 256 threads, 8x4 micro-tile per thread.
#define BM 128
#define BN 64
#define BK 16
__global__ __launch_bounds__(256) void gemm_scaled(
    const float* __restrict__ A, const float* __restrict__ W,
    const float* __restrict__ rowScale, float* __restrict__ C,
    int M, int K)
{
    __shared__ float As[BK][BM + 4];
    __shared__ float Bs[BK][BN];

    const int block_m = blockIdx.y * BM;
    const int block_n = blockIdx.x * BN;
    const int tid = threadIdx.x;
    const int tm = tid >> 4;      // 0..15 -> rows tm*8 .. tm*8+7
    const int tn = tid & 15;      // 0..15 -> cols tn*4 .. tn*4+3

    float acc[8][4];
    #pragma unroll
    for (int i = 0; i < 8; i++)
        #pragma unroll
        for (int j = 0; j < 4; j++) acc[i][j] = 0.0f;

    for (int k0 = 0; k0 < K; k0 += BK) {
        // load A tile: BM x BK = 2048 floats, 8 per thread
        #pragma unroll
        for (int i = 0; i < 8; i++) {
            int idx = tid + i * 256;
            int r = idx / BK;
            int c = idx % BK;
            int gr = block_m + r;
            float v = 0.0f;
            if (gr < M) v = A[gr * K + k0 + c] * rowScale[gr];
            As[c][r] = v;
        }
        // load B tile: BK x BN = 1024 floats, 4 per thread
        #pragma unroll
        for (int i = 0; i < 4; i++) {
            int idx = tid + i * 256;
            int r = idx / BN;
            int c = idx % BN;
            Bs[r][c] = W[(k0 + r) * HID + block_n + c];
        }
        __syncthreads();

        #pragma unroll
        for (int k = 0; k < BK; k++) {
            float a[8], b[4];
            #pragma unroll
            for (int i = 0; i < 8; i++) a[i] = As[k][tm * 8 + i];
            #pragma unroll
            for (int j = 0; j < 4; j++) b[j] = Bs[k][tn * 4 + j];
            #pragma unroll
            for (int i = 0; i < 8; i++)
                #pragma unroll
                for (int j = 0; j < 4; j++)
                    acc[i][j] = fmaf(a[i], b[j], acc[i][j]);
        }
        __syncthreads();
    }

    #pragma unroll
    for (int i = 0; i < 8; i++) {
        int row = block_m + tm * 8 + i;
        if (row < M) {
            float4 v = make_float4(acc[i][0], acc[i][1], acc[i][2], acc[i][3]);
            *reinterpret_cast<float4*>(&C[row * HID + block_n + tn * 4]) = v;
        }
    }
}

// ---------------- edge scatter-add: out[dst[e], :] += feat[src[e], :] ----------------
// one thread per (edge, 4-col chunk): 128 threads cover one edge's 512 cols
__global__ void scatter_add(const float* __restrict__ feat,
                            const int* __restrict__ src, const int* __restrict__ dst,
                            float* __restrict__ out) {
    long long idx = (long long)blockIdx.x * blockDim.x + threadIdx.x;
    int e  = (int)(idx >> 7);
    int c  = ((int)idx & 127) << 2;
    if (e >= N_EDGES) return;
    int s = src[e];
    int d = dst[e];
    float4 v = *reinterpret_cast<const float4*>(feat + s * HID + c);
    float* o = out + d * HID + c;
    atomicAdd(o + 0, v.x);
    atomicAdd(o + 1, v.y);
    atomicAdd(o + 2, v.z);
    atomicAdd(o + 3, v.w);
}

// ---------------- finalize: h = relu(h * din[row] + b[col]) ----------------
__global__ void finalize_relu(float* __restrict__ h, const float* __restrict__ din,
                              const float* __restrict__ b) {
    int i = blockIdx.x * blockDim.x + threadIdx.x;  // over N_NODES*HID/4
    if (i >= N_NODES * HID / 4) return;
    int row = i / (HID / 4);
    int c   = (i % (HID / 4)) * 4;
    float s = din[row];
    float4 v  = reinterpret_cast<float4*>(h)[i];
    float4 bb = *reinterpret_cast<const float4*>(b + c);
    v.x = fmaxf(fmaf(v.x, s, bb.x), 0.f);
    v.y = fmaxf(fmaf(v.y, s, bb.y), 0.f);
    v.z = fmaxf(fmaf(v.z, s, bb.z), 0.f);
    v.w = fmaxf(fmaf(v.w, s, bb.w), 0.f);
    reinterpret_cast<float4*>(h)[i] = v;
}

// ---------------- graph counts (graph_ids sorted, but histogram is cheap) ----------------
__global__ void count_kernel(const int* __restrict__ gid, float* __restrict__ cnt) {
    __shared__ int s[N_GRAPHS];
    if (threadIdx.x < N_GRAPHS) s[threadIdx.x] = 0;
    __syncthreads();
    for (int i = threadIdx.x; i < N_NODES; i += blockDim.x)
        atomicAdd(&s[gid[i]], 1);
    __syncthreads();
    if (threadIdx.x < N_GRAPHS) cnt[threadIdx.x] = (float)s[threadIdx.x];
}

// ---------------- pooling: run-length accumulate (gid sorted) then atomics at boundaries ----------------
#define POOL_CHUNK 160
__global__ void pool_kernel(const float* __restrict__ h, const int* __restrict__ gid,
                            float* __restrict__ pool) {
    __shared__ int sg[POOL_CHUNK];
    int n0 = blockIdx.x * POOL_CHUNK;
    int n1 = min(n0 + POOL_CHUNK, N_NODES);
    for (int i = threadIdx.x; i < n1 - n0; i += blockDim.x) sg[i] = gid[n0 + i];
    __syncthreads();

    int c = threadIdx.x * 4;   // 128 threads x 4 cols = 512
    float4 acc = make_float4(0.f, 0.f, 0.f, 0.f);
    int cur = sg[0];
    for (int n = n0; n < n1; n++) {
        int g = sg[n - n0];
        if (g != cur) {
            float* p = pool + cur * HID + c;
            atomicAdd(p + 0, acc.x); atomicAdd(p + 1, acc.y);
            atomicAdd(p + 2, acc.z); atomicAdd(p + 3, acc.w);
            acc = make_float4(0.f, 0.f, 0.f, 0.f);
            cur = g;
        }
        float4 v = *reinterpret_cast<const float4*>(h + n * HID + c);
        acc.x += v.x; acc.y += v.y; acc.z += v.z; acc.w += v.w;
    }
    float* p = pool + cur * HID + c;
    atomicAdd(p + 0, acc.x); atomicAdd(p + 1, acc.y);
    atomicAdd(p + 2, acc.z); atomicAdd(p + 3, acc.w);
}

__global__ void div_kernel(float* __restrict__ pool, const float* __restrict__ cnt) {
    int i = blockIdx.x * blockDim.x + threadIdx.x;
    if (i < N_GRAPHS * HID) {
        float inv = 1.0f / fmaxf(cnt[i / HID], 1.0f);
        pool[i] *= inv;
    }
}

// ---------------- tiny dense layers for the MLP head ----------------
// out[g, n] = relu( sum_k in[g,k]*W[k,n] + b[n] ),  grid (64, 2), block 256
__global__ void dense512(const float* __restrict__ in, const float* __restrict__ W,
                         const float* __restrict__ b, float* __restrict__ out) {
    __shared__ float sh[HID];
    int g = blockIdx.x;
    for (int i = threadIdx.x; i < HID; i += blockDim.x) sh[i] = in[g * HID + i];
    __syncthreads();
    int n = blockIdx.y * 256 + threadIdx.x;
    float acc = b[n];
    #pragma unroll 8
    for (int k = 0; k < HID; k++)
        acc = fmaf(sh[k], W[k * HID + n], acc);
    out[g * HID + n] = fmaxf(acc, 0.0f);
}

// final classifier: out[g, n] = sum_k in[g,k]*Wc3[k,n] + b[n]; grid 64, block 16
__global__ void dense_out(const float* __restrict__ in, const float* __restrict__ W,
                          const float* __restrict__ b, float* __restrict__ out) {
    int g = blockIdx.x;
    int n = threadIdx.x;   // 0..15
    float acc = b[n];
    for (int k = 0; k < HID; k++)
        acc = fmaf(in[g * HID + k], W[k * N_CLASSES + n], acc);
    out[g * N_CLASSES + n] = acc;
}

// ---------------- launch ----------------
extern "C" void kernel_launch(void* const* d_in, const int* in_sizes, int n_in,
                              void* d_out, int out_size) {
    const float* x    = (const float*)d_in[0];
    const int*   src  = (const int*)  d_in[1];
    const int*   dst  = (const int*)  d_in[2];
    const int*   gid  = (const int*)  d_in[3];
    const float* W1   = (const float*)d_in[4];
    const float* b1   = (const float*)d_in[5];
    const float* W2   = (const float*)d_in[6];
    const float* b2   = (const float*)d_in[7];
    const float* W3   = (const float*)d_in[8];
    const float* b3   = (const float*)d_in[9];
    const float* Wc1  = (const float*)d_in[10];
    const float* bc1  = (const float*)d_in[11];
    const float* Wc2  = (const float*)d_in[12];
    const float* bc2  = (const float*)d_in[13];
    const float* Wc3  = (const float*)d_in[14];
    const float* bc3  = (const float*)d_in[15];
    float* out = (float*)d_out;

    float *bufA, *bufB, *doutv, *dinv, *pool, *cnt, *m1, *m2;
    cudaGetSymbolAddress((void**)&bufA,  g_bufA);
    cudaGetSymbolAddress((void**)&bufB,  g_bufB);
    cudaGetSymbolAddress((void**)&doutv, g_dout);
    cudaGetSymbolAddress((void**)&dinv,  g_din);
    cudaGetSymbolAddress((void**)&pool,  g_pool);
    cudaGetSymbolAddress((void**)&cnt,   g_cnt);
    cudaGetSymbolAddress((void**)&m1,    g_mlp1);
    cudaGetSymbolAddress((void**)&m2,    g_mlp2);

    const int nb_nodes   = (N_NODES + 255) / 256;
    const int nb_edges   = (N_EDGES + 255) / 256;
    const int feat4      = N_NODES * HID / 4;
    const int nb_feat4   = (feat4 + 255) / 256;
    const long long scat = (long long)N_EDGES * (HID / 4);
    const int nb_scat    = (int)((scat + 255) / 256);
    dim3 gemm_grid(HID / BN, (N_NODES + BM - 1) / BM);

    // degrees
    zero_f<<<nb_nodes, 256>>>(doutv, N_NODES);
    zero_f<<<nb_nodes, 256>>>(dinv,  N_NODES);
    deg_kernel<<<nb_edges, 256>>>(src, dst, doutv, dinv);
    isqrt_kernel<<<nb_nodes, 256>>>(doutv, dinv);

    // layer 1
    gemm_scaled<<<gemm_grid, 256>>>(x, W1, doutv, bufA, N_NODES, IN_DIM);
    zero_f4<<<nb_feat4, 256>>>(bufB, feat4);
    scatter_add<<<nb_scat, 256>>>(bufA, src, dst, bufB);
    finalize_relu<<<nb_feat4, 256>>>(bufB, dinv, b1);

    // layer 2
    gemm_scaled<<<gemm_grid, 256>>>(bufB, W2, doutv, bufA, N_NODES, HID);
    zero_f4<<<nb_feat4, 256>>>(bufB, feat4);
    scatter_add<<<nb_scat, 256>>>(bufA, src, dst, bufB);
    finalize_relu<<<nb_feat4, 256>>>(bufB, dinv, b2);

    // layer 3
    gemm_scaled<<<gemm_grid, 256>>>(bufB, W3, doutv, bufA, N_NODES, HID);
    zero_f4<<<nb_feat4, 256>>>(bufB, feat4);
    scatter_add<<<nb_scat, 256>>>(bufA, src, dst, bufB);
    finalize_relu<<<nb_feat4, 256>>>(bufB, dinv, b3);

    // mean pooling
    zero_f<<<(N_GRAPHS * HID + 255) / 256, 256>>>(pool, N_GRAPHS * HID);
    count_kernel<<<1, 256>>>(gid, cnt);
    pool_kernel<<<(N_NODES + POOL_CHUNK - 1) / POOL_CHUNK, 128>>>(bufB, gid, pool);
    div_kernel<<<(N_GRAPHS * HID + 255) / 256, 256>>>(pool, cnt);

    // MLP head
    dense512<<<dim3(N_GRAPHS, 2), 256>>>(pool, Wc1, bc1, m1);
    dense512<<<dim3(N_GRAPHS, 2), 256>>>(m1, Wc2, bc2, m2);
    dense_out<<<N_GRAPHS, 16>>>(m2, Wc3, bc3, out);
}

// round 4
// speedup vs baseline: 1.3900x; 1.3900x over previous
#include <cuda_runtime.h>
#include <cuda_bf16.h>
#include <mma.h>
#include <cstdint>

using namespace nvcuda;

#define N_NODES   20000
#define N_EDGES   160000
#define N_GRAPHS  64
#define IN_DIM    128
#define HID       512
#define N_CLASSES 16
#define MROWS     20096   // 157 * 128, padded so GEMM needs no row guards

// ---------------- scratch (static device globals; no allocation) ----------------
__device__ float g_bufA[MROWS * HID];   // GEMM output / scatter source
__device__ float g_bufB[MROWS * HID];   // scatter target / layer activations
__device__ float g_dout[N_NODES];       // rsqrt(out-degree)
__device__ float g_din [N_NODES];       // rsqrt(in-degree)
__device__ float g_pool[N_GRAPHS * HID];
__device__ float g_cnt [N_GRAPHS];
__device__ float g_mlp1[N_GRAPHS * HID];
__device__ float g_mlp2[N_GRAPHS * HID];
// bf16 split buffers (A rows padded to MROWS)
__device__ __nv_bfloat16 g_Ahi[MROWS * HID];
__device__ __nv_bfloat16 g_Alo[MROWS * HID];
__device__ __nv_bfloat16 g_Whi[HID * HID];   // transposed: [n][k]
__device__ __nv_bfloat16 g_Wlo[HID * HID];

// ---------------- utility kernels ----------------
__global__ void zero_f(float* p, int n) {
    int i = blockIdx.x * blockDim.x + threadIdx.x;
    if (i < n) p[i] = 0.0f;
}
__global__ void zero_f4(float* p, int n4) {
    int i = blockIdx.x * blockDim.x + threadIdx.x;
    if (i < n4) reinterpret_cast<float4*>(p)[i] = make_float4(0.f, 0.f, 0.f, 0.f);
}
__global__ void deg_kernel(const int* __restrict__ src, const int* __restrict__ dst,
                           float* dout, float* din) {
    int e = blockIdx.x * blockDim.x + threadIdx.x;
    if (e < N_EDGES) {
        atomicAdd(&dout[src[e]], 1.0f);
        atomicAdd(&din [dst[e]], 1.0f);
    }
}
__global__ void isqrt_kernel(float* dout, float* din) {
    int i = blockIdx.x * blockDim.x + threadIdx.x;
    if (i < N_NODES) {
        dout[i] = rsqrtf(fmaxf(dout[i], 1.0f));
        din [i] = rsqrtf(fmaxf(din [i], 1.0f));
    }
}

// Split fp32 activation (scaled by rowScale) into bf16 hi + lo
__global__ void split_scaled(const float* __restrict__ in, const float* __restrict__ scale,
                             __nv_bfloat16* __restrict__ hi, __nv_bfloat16* __restrict__ lo,
                             int total4, int K) {
    int i = blockIdx.x * blockDim.x + threadIdx.x;
    if (i >= total4) return;
    int row = (i * 4) / K;
    float s = scale[row];
    float4 v = reinterpret_cast<const float4*>(in)[i];
    v.x *= s; v.y *= s; v.z *= s; v.w *= s;
    __nv_bfloat16 h0 = __float2bfloat16(v.x);
    __nv_bfloat16 h1 = __float2bfloat16(v.y);
    __nv_bfloat16 h2 = __float2bfloat16(v.z);
    __nv_bfloat16 h3 = __float2bfloat16(v.w);
    __nv_bfloat16 l0 = __float2bfloat16(v.x - __bfloat162float(h0));
    __nv_bfloat16 l1 = __float2bfloat16(v.y - __bfloat162float(h1));
    __nv_bfloat16 l2 = __float2bfloat16(v.z - __bfloat162float(h2));
    __nv_bfloat16 l3 = __float2bfloat16(v.w - __bfloat162float(h3));
    __nv_bfloat162* hp = reinterpret_cast<__nv_bfloat162*>(hi) + i * 2;
    __nv_bfloat162* lp = reinterpret_cast<__nv_bfloat162*>(lo) + i * 2;
    hp[0] = __nv_bfloat162(h0, h1); hp[1] = __nv_bfloat162(h2, h3);
    lp[0] = __nv_bfloat162(l0, l1); lp[1] = __nv_bfloat162(l2, l3);
}

// Transpose + split weights: W[k][n] fp32 -> Wt_hi/lo[n][k] bf16
__global__ void wsplit(const float* __restrict__ W,
                       __nv_bfloat16* __restrict__ hi, __nv_bfloat16* __restrict__ lo,
                       int K, int N) {
    int idx = blockIdx.x * blockDim.x + threadIdx.x;
    if (idx >= K * N) return;
    int k = idx / N, n = idx % N;
    float v = W[idx];
    __nv_bfloat16 h = __float2bfloat16(v);
    hi[n * K + k] = h;
    lo[n * K + k] = __float2bfloat16(v - __bfloat162float(h));
}

// ================= WMMA bf16-split GEMM =================
// C[M,512] = Ahi@Bhi^T + Ahi@Blo^T + Alo@Bhi^T  (fp32 accum)
// A: [MROWS][K] row-major bf16 (hi/lo), B: [512][K] row-major bf16 = col-major KxN.
#define GBM 128
#define GBN 128
#define GBK 32
#define LDS_T 40   // 32 + 8 pad (bf16 elems), 80 B row stride (16B aligned)

__global__ __launch_bounds__(256) void gemm_wmma(
    const __nv_bfloat16* __restrict__ Ahi, const __nv_bfloat16* __restrict__ Alo,
    const __nv_bfloat16* __restrict__ Bhi, const __nv_bfloat16* __restrict__ Blo,
    float* __restrict__ C, int K)
{
    extern __shared__ __nv_bfloat16 sm[];
    __nv_bfloat16* sAhi = sm;                       // 128 * 40
    __nv_bfloat16* sAlo = sAhi + GBM * LDS_T;
    __nv_bfloat16* sBhi = sAlo + GBM * LDS_T;
    __nv_bfloat16* sBlo = sBhi + GBN * LDS_T;

    const int tid = threadIdx.x;
    const int wid = tid >> 5;
    const int warp_m = wid >> 2;      // 0..1 -> rows warp_m*64
    const int warp_n = wid & 3;       // 0..3 -> cols warp_n*32
    const int m0 = blockIdx.x * GBM;
    const int n0 = blockIdx.y * GBN;

    wmma::fragment<wmma::accumulator, 16, 16, 16, float> c[4][2];
    #pragma unroll
    for (int i = 0; i < 4; i++)
        #pragma unroll
        for (int j = 0; j < 2; j++) wmma::fill_fragment(c[i][j], 0.0f);

    for (int k0 = 0; k0 < K; k0 += GBK) {
        // Each tile is 128 rows x 32 bf16 = 512 uint4; 256 threads -> 2 uint4 each.
        #pragma unroll
        for (int t = tid; t < 512; t += 256) {
            int r = t >> 2;      // row 0..127
            int q = t & 3;       // uint4 index within the 32-elem row
            const uint4* aH = reinterpret_cast<const uint4*>(Ahi + (size_t)(m0 + r) * K + k0);
            const uint4* aL = reinterpret_cast<const uint4*>(Alo + (size_t)(m0 + r) * K + k0);
            const uint4* bH = reinterpret_cast<const uint4*>(Bhi + (size_t)(n0 + r) * K + k0);
            const uint4* bL = reinterpret_cast<const uint4*>(Blo + (size_t)(n0 + r) * K + k0);
            *reinterpret_cast<uint4*>(sAhi + r * LDS_T + q * 8) = aH[q];
            *reinterpret_cast<uint4*>(sAlo + r * LDS_T + q * 8) = aL[q];
            *reinterpret_cast<uint4*>(sBhi + r * LDS_T + q * 8) = bH[q];
            *reinterpret_cast<uint4*>(sBlo + r * LDS_T + q * 8) = bL[q];
        }
        __syncthreads();

        #pragma unroll
        for (int ks = 0; ks < GBK; ks += 16) {
            wmma::fragment<wmma::matrix_b, 16, 16, 16, __nv_bfloat16, wmma::col_major> bh[2], bl[2];
            #pragma unroll
            for (int j = 0; j < 2; j++) {
                int nn = warp_n * 32 + j * 16;
                wmma::load_matrix_sync(bh[j], sBhi + nn * LDS_T + ks, LDS_T);
                wmma::load_matrix_sync(bl[j], sBlo + nn * LDS_T + ks, LDS_T);
            }
            #pragma unroll
            for (int i = 0; i < 4; i++) {
                int mm = warp_m * 64 + i * 16;
                wmma::fragment<wmma::matrix_a, 16, 16, 16, __nv_bfloat16, wmma::row_major> ah, al;
                wmma::load_matrix_sync(ah, sAhi + mm * LDS_T + ks, LDS_T);
                wmma::load_matrix_sync(al, sAlo + mm * LDS_T + ks, LDS_T);
                #pragma unroll
                for (int j = 0; j < 2; j++) {
                    wmma::mma_sync(c[i][j], ah, bh[j], c[i][j]);
                    wmma::mma_sync(c[i][j], ah, bl[j], c[i][j]);
                    wmma::mma_sync(c[i][j], al, bh[j], c[i][j]);
                }
            }
        }
        __syncthreads();
    }

    // epilogue: direct store (MROWS padding means no row guard needed)
    #pragma unroll
    for (int i = 0; i < 4; i++) {
        int row = m0 + warp_m * 64 + i * 16;
        #pragma unroll
        for (int j = 0; j < 2; j++) {
            int col = n0 + warp_n * 32 + j * 16;
            wmma::store_matrix_sync(C + (size_t)row * HID + col, c[i][j], HID,
                                    wmma::mem_row_major);
        }
    }
}

// ---------------- edge scatter-add ----------------
__global__ void scatter_add(const float* __restrict__ feat,
                            const int* __restrict__ src, const int* __restrict__ dst,
                            float* __restrict__ out) {
    long long idx = (long long)blockIdx.x * blockDim.x + threadIdx.x;
    int e  = (int)(idx >> 7);
    int c  = ((int)idx & 127) << 2;
    if (e >= N_EDGES) return;
    int s = src[e];
    int d = dst[e];
    float4 v = *reinterpret_cast<const float4*>(feat + s * HID + c);
    float* o = out + d * HID + c;
    atomicAdd(o + 0, v.x);
    atomicAdd(o + 1, v.y);
    atomicAdd(o + 2, v.z);
    atomicAdd(o + 3, v.w);
}

// ---------------- finalize: h = relu(h * din[row] + b[col]) ----------------
__global__ void finalize_relu(float* __restrict__ h, const float* __restrict__ din,
                              const float* __restrict__ b) {
    int i = blockIdx.x * blockDim.x + threadIdx.x;
    if (i >= N_NODES * HID / 4) return;
    int row = i / (HID / 4);
    int c   = (i % (HID / 4)) * 4;
    float s = din[row];
    float4 v  = reinterpret_cast<float4*>(h)[i];
    float4 bb = *reinterpret_cast<const float4*>(b + c);
    v.x = fmaxf(fmaf(v.x, s, bb.x), 0.f);
    v.y = fmaxf(fmaf(v.y, s, bb.y), 0.f);
    v.z = fmaxf(fmaf(v.z, s, bb.z), 0.f);
    v.w = fmaxf(fmaf(v.w, s, bb.w), 0.f);
    reinterpret_cast<float4*>(h)[i] = v;
}

// ---------------- pooling ----------------
__global__ void count_kernel(const int* __restrict__ gid, float* __restrict__ cnt) {
    __shared__ int s[N_GRAPHS];
    if (threadIdx.x < N_GRAPHS) s[threadIdx.x] = 0;
    __syncthreads();
    for (int i = threadIdx.x; i < N_NODES; i += blockDim.x)
        atomicAdd(&s[gid[i]], 1);
    __syncthreads();
    if (threadIdx.x < N_GRAPHS) cnt[threadIdx.x] = (float)s[threadIdx.x];
}

#define POOL_CHUNK 160
__global__ void pool_kernel(const float* __restrict__ h, const int* __restrict__ gid,
                            float* __restrict__ pool) {
    __shared__ int sg[POOL_CHUNK];
    int n0 = blockIdx.x * POOL_CHUNK;
    int n1 = min(n0 + POOL_CHUNK, N_NODES);
    for (int i = threadIdx.x; i < n1 - n0; i += blockDim.x) sg[i] = gid[n0 + i];
    __syncthreads();

    int c = threadIdx.x * 4;
    float4 acc = make_float4(0.f, 0.f, 0.f, 0.f);
    int cur = sg[0];
    for (int n = n0; n < n1; n++) {
        int g = sg[n - n0];
        if (g != cur) {
            float* p = pool + cur * HID + c;
            atomicAdd(p + 0, acc.x); atomicAdd(p + 1, acc.y);
            atomicAdd(p + 2, acc.z); atomicAdd(p + 3, acc.w);
            acc = make_float4(0.f, 0.f, 0.f, 0.f);
            cur = g;
        }
        float4 v = *reinterpret_cast<const float4*>(h + n * HID + c);
        acc.x += v.x; acc.y += v.y; acc.z += v.z; acc.w += v.w;
    }
    float* p = pool + cur * HID + c;
    atomicAdd(p + 0, acc.x); atomicAdd(p + 1, acc.y);
    atomicAdd(p + 2, acc.z); atomicAdd(p + 3, acc.w);
}

__global__ void div_kernel(float* __restrict__ pool, const float* __restrict__ cnt) {
    int i = blockIdx.x * blockDim.x + threadIdx.x;
    if (i < N_GRAPHS * HID) {
        float inv = 1.0f / fmaxf(cnt[i / HID], 1.0f);
        pool[i] *= inv;
    }
}

// ---------------- MLP head ----------------
__global__ void dense512(const float* __restrict__ in, const float* __restrict__ W,
                         const float* __restrict__ b, float* __restrict__ out) {
    __shared__ float sh[HID];
    int g = blockIdx.x;
    for (int i = threadIdx.x; i < HID; i += blockDim.x) sh[i] = in[g * HID + i];
    __syncthreads();
    int n = blockIdx.y * 256 + threadIdx.x;
    float acc = b[n];
    #pragma unroll 8
    for (int k = 0; k < HID; k++)
        acc = fmaf(sh[k], W[k * HID + n], acc);
    out[g * HID + n] = fmaxf(acc, 0.0f);
}

__global__ void dense_out(const float* __restrict__ in, const float* __restrict__ W,
                          const float* __restrict__ b, float* __restrict__ out) {
    int g = blockIdx.x;
    int n = threadIdx.x;
    float acc = b[n];
    for (int k = 0; k < HID; k++)
        acc = fmaf(in[g * HID + k], W[k * N_CLASSES + n], acc);
    out[g * N_CLASSES + n] = acc;
}

// ---------------- launch ----------------
extern "C" void kernel_launch(void* const* d_in, const int* in_sizes, int n_in,
                              void* d_out, int out_size) {
    const float* x    = (const float*)d_in[0];
    const int*   src  = (const int*)  d_in[1];
    const int*   dst  = (const int*)  d_in[2];
    const int*   gid  = (const int*)  d_in[3];
    const float* W1   = (const float*)d_in[4];
    const float* b1   = (const float*)d_in[5];
    const float* W2   = (const float*)d_in[6];
    const float* b2   = (const float*)d_in[7];
    const float* W3   = (const float*)d_in[8];
    const float* b3   = (const float*)d_in[9];
    const float* Wc1  = (const float*)d_in[10];
    const float* bc1  = (const float*)d_in[11];
    const float* Wc2  = (const float*)d_in[12];
    const float* bc2  = (const float*)d_in[13];
    const float* Wc3  = (const float*)d_in[14];
    const float* bc3  = (const float*)d_in[15];
    float* out = (float*)d_out;

    float *bufA, *bufB, *doutv, *dinv, *pool, *cnt, *m1, *m2;
    __nv_bfloat16 *Ahi, *Alo, *Whi, *Wlo;
    cudaGetSymbolAddress((void**)&bufA,  g_bufA);
    cudaGetSymbolAddress((void**)&bufB,  g_bufB);
    cudaGetSymbolAddress((void**)&doutv, g_dout);
    cudaGetSymbolAddress((void**)&dinv,  g_din);
    cudaGetSymbolAddress((void**)&pool,  g_pool);
    cudaGetSymbolAddress((void**)&cnt,   g_cnt);
    cudaGetSymbolAddress((void**)&m1,    g_mlp1);
    cudaGetSymbolAddress((void**)&m2,    g_mlp2);
    cudaGetSymbolAddress((void**)&Ahi,   g_Ahi);
    cudaGetSymbolAddress((void**)&Alo,   g_Alo);
    cudaGetSymbolAddress((void**)&Whi,   g_Whi);
    cudaGetSymbolAddress((void**)&Wlo,   g_Wlo);

    const int smem_gemm = 4 * GBM * LDS_T * (int)sizeof(__nv_bfloat16);  // 40960
    cudaFuncSetAttribute(gemm_wmma, cudaFuncAttributeMaxDynamicSharedMemorySize, smem_gemm);

    const int nb_nodes   = (N_NODES + 255) / 256;
    const int nb_edges   = (N_EDGES + 255) / 256;
    const int feat4      = N_NODES * HID / 4;
    const int nb_feat4   = (feat4 + 255) / 256;
    const long long scat = (long long)N_EDGES * (HID / 4);
    const int nb_scat    = (int)((scat + 255) / 256);
    dim3 gemm_grid(MROWS / GBM, HID / GBN);   // (157, 4)

    // degrees
    zero_f<<<nb_nodes, 256>>>(doutv, N_NODES);
    zero_f<<<nb_nodes, 256>>>(dinv,  N_NODES);
    deg_kernel<<<nb_edges, 256>>>(src, dst, doutv, dinv);
    isqrt_kernel<<<nb_nodes, 256>>>(doutv, dinv);

    // layer 1
    {
        wsplit<<<(IN_DIM * HID + 255) / 256, 256>>>(W1, Whi, Wlo, IN_DIM, HID);
        int t4 = N_NODES * IN_DIM / 4;
        split_scaled<<<(t4 + 255) / 256, 256>>>(x, doutv, Ahi, Alo, t4, IN_DIM);
        gemm_wmma<<<gemm_grid, 256, smem_gemm>>>(Ahi, Alo, Whi, Wlo, bufA, IN_DIM);
        zero_f4<<<nb_feat4, 256>>>(bufB, feat4);
        scatter_add<<<nb_scat, 256>>>(bufA, src, dst, bufB);
        finalize_relu<<<nb_feat4, 256>>>(bufB, dinv, b1);
    }
    // layer 2
    {
        wsplit<<<(HID * HID + 255) / 256, 256>>>(W2, Whi, Wlo, HID, HID);
        split_scaled<<<nb_feat4, 256>>>(bufB, doutv, Ahi, Alo, feat4, HID);
        gemm_wmma<<<gemm_grid, 256, smem_gemm>>>(Ahi, Alo, Whi, Wlo, bufA, HID);
        zero_f4<<<nb_feat4, 256>>>(bufB, feat4);
        scatter_add<<<nb_scat, 256>>>(bufA, src, dst, bufB);
        finalize_relu<<<nb_feat4, 256>>>(bufB, dinv, b2);
    }
    // layer 3
    {
        wsplit<<<(HID * HID + 255) / 256, 256>>>(W3, Whi, Wlo, HID, HID);
        split_scaled<<<nb_feat4, 256>>>(bufB, doutv, Ahi, Alo, feat4, HID);
        gemm_wmma<<<gemm_grid, 256, smem_gemm>>>(Ahi, Alo, Whi, Wlo, bufA, HID);
        zero_f4<<<nb_feat4, 256>>>(bufB, feat4);
        scatter_add<<<nb_scat, 256>>>(bufA, src, dst, bufB);
        finalize_relu<<<nb_feat4, 256>>>(bufB, dinv, b3);
    }

    // mean pooling
    zero_f<<<(N_GRAPHS * HID + 255) / 256, 256>>>(pool, N_GRAPHS * HID);
    count_kernel<<<1, 256>>>(gid, cnt);
    pool_kernel<<<(N_NODES + POOL_CHUNK - 1) / POOL_CHUNK, 128>>>(bufB, gid, pool);
    div_kernel<<<(N_GRAPHS * HID + 255) / 256, 256>>>(pool, cnt);

    // MLP head
    dense512<<<dim3(N_GRAPHS, 2), 256>>>(pool, Wc1, bc1, m1);
    dense512<<<dim3(N_GRAPHS, 2), 256>>>(m1, Wc2, bc2, m2);
    dense_out<<<N_GRAPHS, 16>>>(m2, Wc3, bc3, out);
}

// round 5
// speedup vs baseline: 1.4288x; 1.0279x over previous
#include <cuda_runtime.h>
#include <cuda_bf16.h>
#include <mma.h>
#include <cstdint>

using namespace nvcuda;

#define N_NODES   20000
#define N_EDGES   160000
#define N_GRAPHS  64
#define IN_DIM    128
#define HID       512
#define N_CLASSES 16
#define MROWS     20096   // 157 * 128, padded so GEMM needs no row guards

// ---------------- scratch (static device globals; no allocation) ----------------
__device__ float g_bufA[MROWS * HID];   // GEMM output / scatter source
__device__ float g_bufB[MROWS * HID];   // scatter target / layer activations
__device__ float g_dout[N_NODES];       // rsqrt(out-degree)
__device__ float g_din [N_NODES];       // rsqrt(in-degree)
__device__ float g_pool[N_GRAPHS * HID];
__device__ float g_cnt [N_GRAPHS];
__device__ float g_mlp1[N_GRAPHS * HID];
__device__ float g_mlp2[N_GRAPHS * HID];
// bf16 split buffers (A rows padded to MROWS)
__device__ __nv_bfloat16 g_Ahi[MROWS * HID];
__device__ __nv_bfloat16 g_Alo[MROWS * HID];
__device__ __nv_bfloat16 g_Whi[HID * HID];   // transposed: [n][k]
__device__ __nv_bfloat16 g_Wlo[HID * HID];

// ---------------- utility kernels ----------------
__global__ void zero_f(float* p, int n) {
    int i = blockIdx.x * blockDim.x + threadIdx.x;
    if (i < n) p[i] = 0.0f;
}
__global__ void zero_f4(float* p, int n4) {
    int i = blockIdx.x * blockDim.x + threadIdx.x;
    if (i < n4) reinterpret_cast<float4*>(p)[i] = make_float4(0.f, 0.f, 0.f, 0.f);
}
__global__ void deg_kernel(const int* __restrict__ src, const int* __restrict__ dst,
                           float* dout, float* din) {
    int e = blockIdx.x * blockDim.x + threadIdx.x;
    if (e < N_EDGES) {
        atomicAdd(&dout[src[e]], 1.0f);
        atomicAdd(&din [dst[e]], 1.0f);
    }
}
__global__ void isqrt_kernel(float* dout, float* din) {
    int i = blockIdx.x * blockDim.x + threadIdx.x;
    if (i < N_NODES) {
        dout[i] = rsqrtf(fmaxf(dout[i], 1.0f));
        din [i] = rsqrtf(fmaxf(din [i], 1.0f));
    }
}

// Split fp32 activation (scaled by rowScale) into bf16 hi + lo
__global__ void split_scaled(const float* __restrict__ in, const float* __restrict__ scale,
                             __nv_bfloat16* __restrict__ hi, __nv_bfloat16* __restrict__ lo,
                             int total4, int K) {
    int i = blockIdx.x * blockDim.x + threadIdx.x;
    if (i >= total4) return;
    int row = (i * 4) / K;
    float s = scale[row];
    float4 v = reinterpret_cast<const float4*>(in)[i];
    v.x *= s; v.y *= s; v.z *= s; v.w *= s;
    __nv_bfloat16 h0 = __float2bfloat16(v.x);
    __nv_bfloat16 h1 = __float2bfloat16(v.y);
    __nv_bfloat16 h2 = __float2bfloat16(v.z);
    __nv_bfloat16 h3 = __float2bfloat16(v.w);
    __nv_bfloat16 l0 = __float2bfloat16(v.x - __bfloat162float(h0));
    __nv_bfloat16 l1 = __float2bfloat16(v.y - __bfloat162float(h1));
    __nv_bfloat16 l2 = __float2bfloat16(v.z - __bfloat162float(h2));
    __nv_bfloat16 l3 = __float2bfloat16(v.w - __bfloat162float(h3));
    __nv_bfloat162* hp = reinterpret_cast<__nv_bfloat162*>(hi) + i * 2;
    __nv_bfloat162* lp = reinterpret_cast<__nv_bfloat162*>(lo) + i * 2;
    hp[0] = __nv_bfloat162(h0, h1); hp[1] = __nv_bfloat162(h2, h3);
    lp[0] = __nv_bfloat162(l0, l1); lp[1] = __nv_bfloat162(l2, l3);
}

// Fused: v = relu(agg*din + b); optional fp32 out; then split v*dout into bf16 hi/lo
__global__ void finalize_split(const float* __restrict__ agg, const float* __restrict__ din,
                               const float* __restrict__ dout, const float* __restrict__ b,
                               __nv_bfloat16* __restrict__ hi, __nv_bfloat16* __restrict__ lo) {
    int i = blockIdx.x * blockDim.x + threadIdx.x;
    if (i >= N_NODES * HID / 4) return;
    int row = i / (HID / 4);
    int c   = (i % (HID / 4)) * 4;
    float s  = din[row];
    float so = dout[row];
    float4 v  = reinterpret_cast<const float4*>(agg)[i];
    float4 bb = *reinterpret_cast<const float4*>(b + c);
    v.x = fmaxf(fmaf(v.x, s, bb.x), 0.f) * so;
    v.y = fmaxf(fmaf(v.y, s, bb.y), 0.f) * so;
    v.z = fmaxf(fmaf(v.z, s, bb.z), 0.f) * so;
    v.w = fmaxf(fmaf(v.w, s, bb.w), 0.f) * so;
    __nv_bfloat16 h0 = __float2bfloat16(v.x);
    __nv_bfloat16 h1 = __float2bfloat16(v.y);
    __nv_bfloat16 h2 = __float2bfloat16(v.z);
    __nv_bfloat16 h3 = __float2bfloat16(v.w);
    __nv_bfloat16 l0 = __float2bfloat16(v.x - __bfloat162float(h0));
    __nv_bfloat16 l1 = __float2bfloat16(v.y - __bfloat162float(h1));
    __nv_bfloat16 l2 = __float2bfloat16(v.z - __bfloat162float(h2));
    __nv_bfloat16 l3 = __float2bfloat16(v.w - __bfloat162float(h3));
    __nv_bfloat162* hp = reinterpret_cast<__nv_bfloat162*>(hi) + i * 2;
    __nv_bfloat162* lp = reinterpret_cast<__nv_bfloat162*>(lo) + i * 2;
    hp[0] = __nv_bfloat162(h0, h1); hp[1] = __nv_bfloat162(h2, h3);
    lp[0] = __nv_bfloat162(l0, l1); lp[1] = __nv_bfloat162(l2, l3);
}

// Transpose + split weights: W[k][n] fp32 -> Wt_hi/lo[n][k] bf16
__global__ void wsplit(const float* __restrict__ W,
                       __nv_bfloat16* __restrict__ hi, __nv_bfloat16* __restrict__ lo,
                       int K, int N) {
    int idx = blockIdx.x * blockDim.x + threadIdx.x;
    if (idx >= K * N) return;
    int k = idx / N, n = idx % N;
    float v = W[idx];
    __nv_bfloat16 h = __float2bfloat16(v);
    hi[n * K + k] = h;
    lo[n * K + k] = __float2bfloat16(v - __bfloat162float(h));
}

// ================= WMMA bf16-split GEMM, cp.async 2-stage pipeline =================
// C[M,512] = Ahi@Bhi^T + Ahi@Blo^T + Alo@Bhi^T  (fp32 accum)
// Block tile 128x256, warp tile 64x64 (8 warps, 2x4), GBK=32.
#define GBM 128
#define GBN 256
#define GBK 32
#define LDS_T 40                      // 32 + 8 pad bf16 elems (80B stride)
#define STAGE_ROWS 768                // Ahi 128 + Alo 128 + Bhi 256 + Blo 256
#define STAGE_ELEMS (STAGE_ROWS * LDS_T)

__device__ __forceinline__ void cp16(__nv_bfloat16* smem_dst, const __nv_bfloat16* gsrc) {
    uint32_t s = (uint32_t)__cvta_generic_to_shared(smem_dst);
    asm volatile("cp.async.cg.shared.global [%0], [%1], 16;" :: "r"(s), "l"(gsrc));
}

__device__ __forceinline__ void load_stage(
    const __nv_bfloat16* __restrict__ Ahi, const __nv_bfloat16* __restrict__ Alo,
    const __nv_bfloat16* __restrict__ Bhi, const __nv_bfloat16* __restrict__ Blo,
    __nv_bfloat16* stage, int m0, int n0, int k0, int K, int tid)
{
    // 768 rows x 64B = 3072 16B chunks; 256 threads -> 12 each
    #pragma unroll
    for (int i = 0; i < 12; i++) {
        int o   = tid + i * 256;
        int row = o >> 2;
        int q   = o & 3;
        const __nv_bfloat16* g;
        if      (row < 128) g = Ahi + (size_t)(m0 + row)       * K + k0;
        else if (row < 256) g = Alo + (size_t)(m0 + row - 128) * K + k0;
        else if (row < 512) g = Bhi + (size_t)(n0 + row - 256) * K + k0;
        else                g = Blo + (size_t)(n0 + row - 512) * K + k0;
        cp16(stage + row * LDS_T + q * 8, g + q * 8);
    }
}

__global__ __launch_bounds__(256, 1) void gemm_wmma(
    const __nv_bfloat16* __restrict__ Ahi, const __nv_bfloat16* __restrict__ Alo,
    const __nv_bfloat16* __restrict__ Bhi, const __nv_bfloat16* __restrict__ Blo,
    float* __restrict__ C, int K)
{
    extern __shared__ __nv_bfloat16 sm[];
    const int tid = threadIdx.x;
    const int wid = tid >> 5;
    const int warp_m = wid >> 2;      // 0..1 -> rows warp_m*64
    const int warp_n = wid & 3;       // 0..3 -> cols warp_n*64
    const int m0 = blockIdx.x * GBM;
    const int n0 = blockIdx.y * GBN;

    wmma::fragment<wmma::accumulator, 16, 16, 16, float> c[4][4];
    #pragma unroll
    for (int i = 0; i < 4; i++)
        #pragma unroll
        for (int j = 0; j < 4; j++) wmma::fill_fragment(c[i][j], 0.0f);

    const int nchunks = K / GBK;

    load_stage(Ahi, Alo, Bhi, Blo, sm, m0, n0, 0, K, tid);
    asm volatile("cp.async.commit_group;");

    for (int ch = 0; ch < nchunks; ch++) {
        __nv_bfloat16* st = sm + (ch & 1) * STAGE_ELEMS;
        if (ch + 1 < nchunks) {
            load_stage(Ahi, Alo, Bhi, Blo, sm + ((ch + 1) & 1) * STAGE_ELEMS,
                       m0, n0, (ch + 1) * GBK, K, tid);
            asm volatile("cp.async.commit_group;");
            asm volatile("cp.async.wait_group 1;");
        } else {
            asm volatile("cp.async.wait_group 0;");
        }
        __syncthreads();

        __nv_bfloat16* sAhi = st;
        __nv_bfloat16* sAlo = st + 128 * LDS_T;
        __nv_bfloat16* sBhi = st + 256 * LDS_T;
        __nv_bfloat16* sBlo = st + 512 * LDS_T;

        #pragma unroll
        for (int ks = 0; ks < GBK; ks += 16) {
            wmma::fragment<wmma::matrix_b, 16, 16, 16, __nv_bfloat16, wmma::col_major> bh[4], bl[4];
            #pragma unroll
            for (int j = 0; j < 4; j++) {
                int nn = warp_n * 64 + j * 16;
                wmma::load_matrix_sync(bh[j], sBhi + nn * LDS_T + ks, LDS_T);
                wmma::load_matrix_sync(bl[j], sBlo + nn * LDS_T + ks, LDS_T);
            }
            #pragma unroll
            for (int i = 0; i < 4; i++) {
                int mm = warp_m * 64 + i * 16;
                wmma::fragment<wmma::matrix_a, 16, 16, 16, __nv_bfloat16, wmma::row_major> ah, al;
                wmma::load_matrix_sync(ah, sAhi + mm * LDS_T + ks, LDS_T);
                wmma::load_matrix_sync(al, sAlo + mm * LDS_T + ks, LDS_T);
                #pragma unroll
                for (int j = 0; j < 4; j++) {
                    wmma::mma_sync(c[i][j], ah, bh[j], c[i][j]);
                    wmma::mma_sync(c[i][j], ah, bl[j], c[i][j]);
                    wmma::mma_sync(c[i][j], al, bh[j], c[i][j]);
                }
            }
        }
        __syncthreads();
    }

    // epilogue: direct store (MROWS padding means no row guard needed)
    #pragma unroll
    for (int i = 0; i < 4; i++) {
        int row = m0 + warp_m * 64 + i * 16;
        #pragma unroll
        for (int j = 0; j < 4; j++) {
            int col = n0 + warp_n * 64 + j * 16;
            wmma::store_matrix_sync(C + (size_t)row * HID + col, c[i][j], HID,
                                    wmma::mem_row_major);
        }
    }
}

// ---------------- edge scatter-add ----------------
__global__ void scatter_add(const float* __restrict__ feat,
                            const int* __restrict__ src, const int* __restrict__ dst,
                            float* __restrict__ out) {
    long long idx = (long long)blockIdx.x * blockDim.x + threadIdx.x;
    int e  = (int)(idx >> 7);
    int c  = ((int)idx & 127) << 2;
    if (e >= N_EDGES) return;
    int s = src[e];
    int d = dst[e];
    float4 v = *reinterpret_cast<const float4*>(feat + s * HID + c);
    float* o = out + d * HID + c;
    atomicAdd(o + 0, v.x);
    atomicAdd(o + 1, v.y);
    atomicAdd(o + 2, v.z);
    atomicAdd(o + 3, v.w);
}

// ---------------- finalize (layer 3 only): h = relu(h * din[row] + b[col]) ----------------
__global__ void finalize_relu(float* __restrict__ h, const float* __restrict__ din,
                              const float* __restrict__ b) {
    int i = blockIdx.x * blockDim.x + threadIdx.x;
    if (i >= N_NODES * HID / 4) return;
    int row = i / (HID / 4);
    int c   = (i % (HID / 4)) * 4;
    float s = din[row];
    float4 v  = reinterpret_cast<float4*>(h)[i];
    float4 bb = *reinterpret_cast<const float4*>(b + c);
    v.x = fmaxf(fmaf(v.x, s, bb.x), 0.f);
    v.y = fmaxf(fmaf(v.y, s, bb.y), 0.f);
    v.z = fmaxf(fmaf(v.z, s, bb.z), 0.f);
    v.w = fmaxf(fmaf(v.w, s, bb.w), 0.f);
    reinterpret_cast<float4*>(h)[i] = v;
}

// ---------------- pooling ----------------
__global__ void count_kernel(const int* __restrict__ gid, float* __restrict__ cnt) {
    __shared__ int s[N_GRAPHS];
    if (threadIdx.x < N_GRAPHS) s[threadIdx.x] = 0;
    __syncthreads();
    for (int i = threadIdx.x; i < N_NODES; i += blockDim.x)
        atomicAdd(&s[gid[i]], 1);
    __syncthreads();
    if (threadIdx.x < N_GRAPHS) cnt[threadIdx.x] = (float)s[threadIdx.x];
}

#define POOL_CHUNK 160
__global__ void pool_kernel(const float* __restrict__ h, const int* __restrict__ gid,
                            float* __restrict__ pool) {
    __shared__ int sg[POOL_CHUNK];
    int n0 = blockIdx.x * POOL_CHUNK;
    int n1 = min(n0 + POOL_CHUNK, N_NODES);
    for (int i = threadIdx.x; i < n1 - n0; i += blockDim.x) sg[i] = gid[n0 + i];
    __syncthreads();

    int c = threadIdx.x * 4;
    float4 acc = make_float4(0.f, 0.f, 0.f, 0.f);
    int cur = sg[0];
    for (int n = n0; n < n1; n++) {
        int g = sg[n - n0];
        if (g != cur) {
            float* p = pool + cur * HID + c;
            atomicAdd(p + 0, acc.x); atomicAdd(p + 1, acc.y);
            atomicAdd(p + 2, acc.z); atomicAdd(p + 3, acc.w);
            acc = make_float4(0.f, 0.f, 0.f, 0.f);
            cur = g;
        }
        float4 v = *reinterpret_cast<const float4*>(h + n * HID + c);
        acc.x += v.x; acc.y += v.y; acc.z += v.z; acc.w += v.w;
    }
    float* p = pool + cur * HID + c;
    atomicAdd(p + 0, acc.x); atomicAdd(p + 1, acc.y);
    atomicAdd(p + 2, acc.z); atomicAdd(p + 3, acc.w);
}

__global__ void div_kernel(float* __restrict__ pool, const float* __restrict__ cnt) {
    int i = blockIdx.x * blockDim.x + threadIdx.x;
    if (i < N_GRAPHS * HID) {
        float inv = 1.0f / fmaxf(cnt[i / HID], 1.0f);
        pool[i] *= inv;
    }
}

// ---------------- MLP head ----------------
__global__ void dense512(const float* __restrict__ in, const float* __restrict__ W,
                         const float* __restrict__ b, float* __restrict__ out) {
    __shared__ float sh[HID];
    int g = blockIdx.x;
    for (int i = threadIdx.x; i < HID; i += blockDim.x) sh[i] = in[g * HID + i];
    __syncthreads();
    int n = blockIdx.y * 256 + threadIdx.x;
    float acc = b[n];
    #pragma unroll 8
    for (int k = 0; k < HID; k++)
        acc = fmaf(sh[k], W[k * HID + n], acc);
    out[g * HID + n] = fmaxf(acc, 0.0f);
}

__global__ void dense_out(const float* __restrict__ in, const float* __restrict__ W,
                          const float* __restrict__ b, float* __restrict__ out) {
    int g = blockIdx.x;
    int n = threadIdx.x;
    float acc = b[n];
    for (int k = 0; k < HID; k++)
        acc = fmaf(in[g * HID + k], W[k * N_CLASSES + n], acc);
    out[g * N_CLASSES + n] = acc;
}

// ---------------- launch ----------------
extern "C" void kernel_launch(void* const* d_in, const int* in_sizes, int n_in,
                              void* d_out, int out_size) {
    const float* x    = (const float*)d_in[0];
    const int*   src  = (const int*)  d_in[1];
    const int*   dst  = (const int*)  d_in[2];
    const int*   gid  = (const int*)  d_in[3];
    const float* W1   = (const float*)d_in[4];
    const float* b1   = (const float*)d_in[5];
    const float* W2   = (const float*)d_in[6];
    const float* b2   = (const float*)d_in[7];
    const float* W3   = (const float*)d_in[8];
    const float* b3   = (const float*)d_in[9];
    const float* Wc1  = (const float*)d_in[10];
    const float* bc1  = (const float*)d_in[11];
    const float* Wc2  = (const float*)d_in[12];
    const float* bc2  = (const float*)d_in[13];
    const float* Wc3  = (const float*)d_in[14];
    const float* bc3  = (const float*)d_in[15];
    float* out = (float*)d_out;

    float *bufA, *bufB, *doutv, *dinv, *pool, *cnt, *m1, *m2;
    __nv_bfloat16 *Ahi, *Alo, *Whi, *Wlo;
    cudaGetSymbolAddress((void**)&bufA,  g_bufA);
    cudaGetSymbolAddress((void**)&bufB,  g_bufB);
    cudaGetSymbolAddress((void**)&doutv, g_dout);
    cudaGetSymbolAddress((void**)&dinv,  g_din);
    cudaGetSymbolAddress((void**)&pool,  g_pool);
    cudaGetSymbolAddress((void**)&cnt,   g_cnt);
    cudaGetSymbolAddress((void**)&m1,    g_mlp1);
    cudaGetSymbolAddress((void**)&m2,    g_mlp2);
    cudaGetSymbolAddress((void**)&Ahi,   g_Ahi);
    cudaGetSymbolAddress((void**)&Alo,   g_Alo);
    cudaGetSymbolAddress((void**)&Whi,   g_Whi);
    cudaGetSymbolAddress((void**)&Wlo,   g_Wlo);

    const int smem_gemm = 2 * STAGE_ELEMS * (int)sizeof(__nv_bfloat16);  // 122880
    cudaFuncSetAttribute(gemm_wmma, cudaFuncAttributeMaxDynamicSharedMemorySize, smem_gemm);

    const int nb_nodes   = (N_NODES + 255) / 256;
    const int nb_edges   = (N_EDGES + 255) / 256;
    const int feat4      = N_NODES * HID / 4;
    const int nb_feat4   = (feat4 + 255) / 256;
    const long long scat = (long long)N_EDGES * (HID / 4);
    const int nb_scat    = (int)((scat + 255) / 256);
    dim3 gemm_grid(MROWS / GBM, HID / GBN);   // (157, 2)

    // degrees
    zero_f<<<nb_nodes, 256>>>(doutv, N_NODES);
    zero_f<<<nb_nodes, 256>>>(dinv,  N_NODES);
    deg_kernel<<<nb_edges, 256>>>(src, dst, doutv, dinv);
    isqrt_kernel<<<nb_nodes, 256>>>(doutv, dinv);

    // layer 1
    {
        wsplit<<<(IN_DIM * HID + 255) / 256, 256>>>(W1, Whi, Wlo, IN_DIM, HID);
        int t4 = N_NODES * IN_DIM / 4;
        split_scaled<<<(t4 + 255) / 256, 256>>>(x, doutv, Ahi, Alo, t4, IN_DIM);
        gemm_wmma<<<gemm_grid, 256, smem_gemm>>>(Ahi, Alo, Whi, Wlo, bufA, IN_DIM);
        zero_f4<<<nb_feat4, 256>>>(bufB, feat4);
        scatter_add<<<nb_scat, 256>>>(bufA, src, dst, bufB);
        finalize_split<<<nb_feat4, 256>>>(bufB, dinv, doutv, b1, Ahi, Alo);
    }
    // layer 2
    {
        wsplit<<<(HID * HID + 255) / 256, 256>>>(W2, Whi, Wlo, HID, HID);
        gemm_wmma<<<gemm_grid, 256, smem_gemm>>>(Ahi, Alo, Whi, Wlo, bufA, HID);
        zero_f4<<<nb_feat4, 256>>>(bufB, feat4);
        scatter_add<<<nb_scat, 256>>>(bufA, src, dst, bufB);
        finalize_split<<<nb_feat4, 256>>>(bufB, dinv, doutv, b2, Ahi, Alo);
    }
    // layer 3
    {
        wsplit<<<(HID * HID + 255) / 256, 256>>>(W3, Whi, Wlo, HID, HID);
        gemm_wmma<<<gemm_grid, 256, smem_gemm>>>(Ahi, Alo, Whi, Wlo, bufA, HID);
        zero_f4<<<nb_feat4, 256>>>(bufB, feat4);
        scatter_add<<<nb_scat, 256>>>(bufA, src, dst, bufB);
        finalize_relu<<<nb_feat4, 256>>>(bufB, dinv, b3);
    }

    // mean pooling
    zero_f<<<(N_GRAPHS * HID + 255) / 256, 256>>>(pool, N_GRAPHS * HID);
    count_kernel<<<1, 256>>>(gid, cnt);
    pool_kernel<<<(N_NODES + POOL_CHUNK - 1) / POOL_CHUNK, 128>>>(bufB, gid, pool);
    div_kernel<<<(N_GRAPHS * HID + 255) / 256, 256>>>(pool, cnt);

    // MLP head
    dense512<<<dim3(N_GRAPHS, 2), 256>>>(pool, Wc1, bc1, m1);
    dense512<<<dim3(N_GRAPHS, 2), 256>>>(m1, Wc2, bc2, m2);
    dense_out<<<N_GRAPHS, 16>>>(m2, Wc3, bc3, out);
}

// round 6
// speedup vs baseline: 2.4659x; 1.7259x over previous
#include <cuda_runtime.h>
#include <cuda_bf16.h>
#include <mma.h>
#include <cstdint>

using namespace nvcuda;

#define N_NODES   20000
#define N_EDGES   160000
#define N_GRAPHS  64
#define IN_DIM    128
#define HID       512
#define N_CLASSES 16
#define MROWS     20096   // 157 * 128, padded so GEMM needs no row guards

// ---------------- scratch (static device globals; no allocation) ----------------
__device__ float g_bufA[MROWS * HID];   // GEMM output (gather source)
__device__ float g_bufB[MROWS * HID];   // layer-3 fp32 activations (pool input)
__device__ float g_dout[N_NODES];       // rsqrt(out-degree)
__device__ float g_din [N_NODES];       // rsqrt(in-degree)
__device__ float g_pool[N_GRAPHS * HID];
__device__ float g_cnt [N_GRAPHS];
__device__ float g_mlp1[N_GRAPHS * HID];
__device__ float g_mlp2[N_GRAPHS * HID];
// CSR (by dst)
__device__ int g_cin   [N_NODES];
__device__ int g_cout  [N_NODES];
__device__ int g_rowoff[N_NODES + 1];
__device__ int g_cursor[N_NODES];
__device__ int g_csrc  [N_EDGES];
// bf16 split buffers (A rows padded to MROWS)
__device__ __nv_bfloat16 g_Ahi[MROWS * HID];
__device__ __nv_bfloat16 g_Alo[MROWS * HID];
__device__ __nv_bfloat16 g_Whi[HID * HID];   // transposed: [n][k]
__device__ __nv_bfloat16 g_Wlo[HID * HID];

// ---------------- utility kernels ----------------
__global__ void zero_i2(int* a, int* b, int n) {
    int i = blockIdx.x * blockDim.x + threadIdx.x;
    if (i < n) { a[i] = 0; b[i] = 0; }
}
__global__ void zero_f(float* p, int n) {
    int i = blockIdx.x * blockDim.x + threadIdx.x;
    if (i < n) p[i] = 0.0f;
}
__global__ void deg_kernel(const int* __restrict__ src, const int* __restrict__ dst,
                           int* cout_, int* cin_) {
    int e = blockIdx.x * blockDim.x + threadIdx.x;
    if (e < N_EDGES) {
        atomicAdd(&cout_[src[e]], 1);
        atomicAdd(&cin_ [dst[e]], 1);
    }
}

// Single-block exclusive scan over cin -> rowoff/cursor; also din/dout rsqrt.
__global__ __launch_bounds__(1024) void scan_kernel(
    const int* __restrict__ cin_, const int* __restrict__ cout_,
    int* __restrict__ rowoff, int* __restrict__ cursor,
    float* __restrict__ din, float* __restrict__ dout)
{
    __shared__ int tmp[1024];
    __shared__ int running;
    int tid = threadIdx.x;
    if (tid == 0) running = 0;
    __syncthreads();
    for (int c0 = 0; c0 < N_NODES; c0 += 1024) {
        int idx = c0 + tid;
        int v = (idx < N_NODES) ? cin_[idx] : 0;
        tmp[tid] = v;
        __syncthreads();
        // Hillis-Steele inclusive scan
        #pragma unroll
        for (int off = 1; off < 1024; off <<= 1) {
            int t = (tid >= off) ? tmp[tid - off] : 0;
            __syncthreads();
            tmp[tid] += t;
            __syncthreads();
        }
        int excl = running + tmp[tid] - v;
        if (idx < N_NODES) {
            rowoff[idx] = excl;
            cursor[idx] = excl;
            din [idx] = rsqrtf(fmaxf((float)cin_ [idx], 1.0f));
            dout[idx] = rsqrtf(fmaxf((float)cout_[idx], 1.0f));
        }
        __syncthreads();
        if (tid == 1023) running += tmp[1023];
        __syncthreads();
    }
    if (tid == 0) rowoff[N_NODES] = running;
}

__global__ void bin_kernel(const int* __restrict__ src, const int* __restrict__ dst,
                           int* __restrict__ cursor, int* __restrict__ csrc) {
    int e = blockIdx.x * blockDim.x + threadIdx.x;
    if (e < N_EDGES) {
        int pos = atomicAdd(&cursor[dst[e]], 1);
        csrc[pos] = src[e];
    }
}

// Split fp32 activation (scaled by rowScale) into bf16 hi + lo  (layer-1 input)
__global__ void split_scaled(const float* __restrict__ in, const float* __restrict__ scale,
                             __nv_bfloat16* __restrict__ hi, __nv_bfloat16* __restrict__ lo,
                             int total4, int K) {
    int i = blockIdx.x * blockDim.x + threadIdx.x;
    if (i >= total4) return;
    int row = (i * 4) / K;
    float s = scale[row];
    float4 v = reinterpret_cast<const float4*>(in)[i];
    v.x *= s; v.y *= s; v.z *= s; v.w *= s;
    __nv_bfloat16 h0 = __float2bfloat16(v.x);
    __nv_bfloat16 h1 = __float2bfloat16(v.y);
    __nv_bfloat16 h2 = __float2bfloat16(v.z);
    __nv_bfloat16 h3 = __float2bfloat16(v.w);
    __nv_bfloat16 l0 = __float2bfloat16(v.x - __bfloat162float(h0));
    __nv_bfloat16 l1 = __float2bfloat16(v.y - __bfloat162float(h1));
    __nv_bfloat16 l2 = __float2bfloat16(v.z - __bfloat162float(h2));
    __nv_bfloat16 l3 = __float2bfloat16(v.w - __bfloat162float(h3));
    __nv_bfloat162* hp = reinterpret_cast<__nv_bfloat162*>(hi) + i * 2;
    __nv_bfloat162* lp = reinterpret_cast<__nv_bfloat162*>(lo) + i * 2;
    hp[0] = __nv_bfloat162(h0, h1); hp[1] = __nv_bfloat162(h2, h3);
    lp[0] = __nv_bfloat162(l0, l1); lp[1] = __nv_bfloat162(l2, l3);
}

// Transpose + split weights: W[k][n] fp32 -> Wt_hi/lo[n][k] bf16
__global__ void wsplit(const float* __restrict__ W,
                       __nv_bfloat16* __restrict__ hi, __nv_bfloat16* __restrict__ lo,
                       int K, int N) {
    int idx = blockIdx.x * blockDim.x + threadIdx.x;
    if (idx >= K * N) return;
    int k = idx / N, n = idx % N;
    float v = W[idx];
    __nv_bfloat16 h = __float2bfloat16(v);
    hi[n * K + k] = h;
    lo[n * K + k] = __float2bfloat16(v - __bfloat162float(h));
}

// ========== fused CSR gather + finalize (+ split) — the atomic-free aggregation ==========
// One block per dst node; 128 threads, each owns 4 contiguous cols.
// mode 0: write (relu(acc*din+b))*dout split into Ahi/Alo (next layer input)
// mode 1: write relu(acc*din+b) fp32 (layer 3 -> pooling)
__global__ __launch_bounds__(128) void gather_fin(
    const float* __restrict__ feat, const int* __restrict__ csrc,
    const int* __restrict__ rowoff,
    const float* __restrict__ din, const float* __restrict__ dout,
    const float* __restrict__ b,
    __nv_bfloat16* __restrict__ hi, __nv_bfloat16* __restrict__ lo,
    float* __restrict__ f32out, int mode)
{
    __shared__ int sidx[256];
    const int n   = blockIdx.x;
    const int tid = threadIdx.x;
    const int beg = rowoff[n];
    const int end = rowoff[n + 1];
    const int deg = end - beg;
    const int nl  = min(deg, 256);
    for (int i = tid; i < nl; i += 128) sidx[i] = csrc[beg + i];
    __syncthreads();

    const int c = tid * 4;
    float4 acc = make_float4(0.f, 0.f, 0.f, 0.f);
    int i = 0;
    for (; i + 4 <= nl; i += 4) {
        const float4 v0 = *reinterpret_cast<const float4*>(feat + (size_t)sidx[i]     * HID + c);
        const float4 v1 = *reinterpret_cast<const float4*>(feat + (size_t)sidx[i + 1] * HID + c);
        const float4 v2 = *reinterpret_cast<const float4*>(feat + (size_t)sidx[i + 2] * HID + c);
        const float4 v3 = *reinterpret_cast<const float4*>(feat + (size_t)sidx[i + 3] * HID + c);
        acc.x += v0.x + v1.x + v2.x + v3.x;
        acc.y += v0.y + v1.y + v2.y + v3.y;
        acc.z += v0.z + v1.z + v2.z + v3.z;
        acc.w += v0.w + v1.w + v2.w + v3.w;
    }
    for (; i < nl; i++) {
        const float4 v = *reinterpret_cast<const float4*>(feat + (size_t)sidx[i] * HID + c);
        acc.x += v.x; acc.y += v.y; acc.z += v.z; acc.w += v.w;
    }
    for (int e = beg + 256; e < end; e++) {           // overflow tail (deg > 256)
        int s = csrc[e];
        const float4 v = *reinterpret_cast<const float4*>(feat + (size_t)s * HID + c);
        acc.x += v.x; acc.y += v.y; acc.z += v.z; acc.w += v.w;
    }

    const float s = din[n];
    const float4 bb = *reinterpret_cast<const float4*>(b + c);
    acc.x = fmaxf(fmaf(acc.x, s, bb.x), 0.f);
    acc.y = fmaxf(fmaf(acc.y, s, bb.y), 0.f);
    acc.z = fmaxf(fmaf(acc.z, s, bb.z), 0.f);
    acc.w = fmaxf(fmaf(acc.w, s, bb.w), 0.f);

    if (mode == 0) {
        const float so = dout[n];
        acc.x *= so; acc.y *= so; acc.z *= so; acc.w *= so;
        __nv_bfloat16 h0 = __float2bfloat16(acc.x);
        __nv_bfloat16 h1 = __float2bfloat16(acc.y);
        __nv_bfloat16 h2 = __float2bfloat16(acc.z);
        __nv_bfloat16 h3 = __float2bfloat16(acc.w);
        __nv_bfloat16 l0 = __float2bfloat16(acc.x - __bfloat162float(h0));
        __nv_bfloat16 l1 = __float2bfloat16(acc.y - __bfloat162float(h1));
        __nv_bfloat16 l2 = __float2bfloat16(acc.z - __bfloat162float(h2));
        __nv_bfloat16 l3 = __float2bfloat16(acc.w - __bfloat162float(h3));
        size_t o = (size_t)n * HID + c;
        *reinterpret_cast<__nv_bfloat162*>(hi + o)     = __nv_bfloat162(h0, h1);
        *reinterpret_cast<__nv_bfloat162*>(hi + o + 2) = __nv_bfloat162(h2, h3);
        *reinterpret_cast<__nv_bfloat162*>(lo + o)     = __nv_bfloat162(l0, l1);
        *reinterpret_cast<__nv_bfloat162*>(lo + o + 2) = __nv_bfloat162(l2, l3);
    } else {
        *reinterpret_cast<float4*>(f32out + (size_t)n * HID + c) = acc;
    }
}

// ================= WMMA bf16-split GEMM, cp.async 2-stage pipeline =================
#define GBM 128
#define GBN 256
#define GBK 32
#define LDS_T 40                      // 32 + 8 pad bf16 elems (80B stride)
#define STAGE_ROWS 768                // Ahi 128 + Alo 128 + Bhi 256 + Blo 256
#define STAGE_ELEMS (STAGE_ROWS * LDS_T)

__device__ __forceinline__ void cp16(__nv_bfloat16* smem_dst, const __nv_bfloat16* gsrc) {
    uint32_t s = (uint32_t)__cvta_generic_to_shared(smem_dst);
    asm volatile("cp.async.cg.shared.global [%0], [%1], 16;" :: "r"(s), "l"(gsrc));
}

__device__ __forceinline__ void load_stage(
    const __nv_bfloat16* __restrict__ Ahi, const __nv_bfloat16* __restrict__ Alo,
    const __nv_bfloat16* __restrict__ Bhi, const __nv_bfloat16* __restrict__ Blo,
    __nv_bfloat16* stage, int m0, int n0, int k0, int K, int tid)
{
    #pragma unroll
    for (int i = 0; i < 12; i++) {
        int o   = tid + i * 256;
        int row = o >> 2;
        int q   = o & 3;
        const __nv_bfloat16* g;
        if      (row < 128) g = Ahi + (size_t)(m0 + row)       * K + k0;
        else if (row < 256) g = Alo + (size_t)(m0 + row - 128) * K + k0;
        else if (row < 512) g = Bhi + (size_t)(n0 + row - 256) * K + k0;
        else                g = Blo + (size_t)(n0 + row - 512) * K + k0;
        cp16(stage + row * LDS_T + q * 8, g + q * 8);
    }
}

__global__ __launch_bounds__(256, 1) void gemm_wmma(
    const __nv_bfloat16* __restrict__ Ahi, const __nv_bfloat16* __restrict__ Alo,
    const __nv_bfloat16* __restrict__ Bhi, const __nv_bfloat16* __restrict__ Blo,
    float* __restrict__ C, int K)
{
    extern __shared__ __nv_bfloat16 sm[];
    const int tid = threadIdx.x;
    const int wid = tid >> 5;
    const int warp_m = wid >> 2;
    const int warp_n = wid & 3;
    const int m0 = blockIdx.x * GBM;
    const int n0 = blockIdx.y * GBN;

    wmma::fragment<wmma::accumulator, 16, 16, 16, float> c[4][4];
    #pragma unroll
    for (int i = 0; i < 4; i++)
        #pragma unroll
        for (int j = 0; j < 4; j++) wmma::fill_fragment(c[i][j], 0.0f);

    const int nchunks = K / GBK;

    load_stage(Ahi, Alo, Bhi, Blo, sm, m0, n0, 0, K, tid);
    asm volatile("cp.async.commit_group;");

    for (int ch = 0; ch < nchunks; ch++) {
        __nv_bfloat16* st = sm + (ch & 1) * STAGE_ELEMS;
        if (ch + 1 < nchunks) {
            load_stage(Ahi, Alo, Bhi, Blo, sm + ((ch + 1) & 1) * STAGE_ELEMS,
                       m0, n0, (ch + 1) * GBK, K, tid);
            asm volatile("cp.async.commit_group;");
            asm volatile("cp.async.wait_group 1;");
        } else {
            asm volatile("cp.async.wait_group 0;");
        }
        __syncthreads();

        __nv_bfloat16* sAhi = st;
        __nv_bfloat16* sAlo = st + 128 * LDS_T;
        __nv_bfloat16* sBhi = st + 256 * LDS_T;
        __nv_bfloat16* sBlo = st + 512 * LDS_T;

        #pragma unroll
        for (int ks = 0; ks < GBK; ks += 16) {
            wmma::fragment<wmma::matrix_b, 16, 16, 16, __nv_bfloat16, wmma::col_major> bh[4], bl[4];
            #pragma unroll
            for (int j = 0; j < 4; j++) {
                int nn = warp_n * 64 + j * 16;
                wmma::load_matrix_sync(bh[j], sBhi + nn * LDS_T + ks, LDS_T);
                wmma::load_matrix_sync(bl[j], sBlo + nn * LDS_T + ks, LDS_T);
            }
            #pragma unroll
            for (int i = 0; i < 4; i++) {
                int mm = warp_m * 64 + i * 16;
                wmma::fragment<wmma::matrix_a, 16, 16, 16, __nv_bfloat16, wmma::row_major> ah, al;
                wmma::load_matrix_sync(ah, sAhi + mm * LDS_T + ks, LDS_T);
                wmma::load_matrix_sync(al, sAlo + mm * LDS_T + ks, LDS_T);
                #pragma unroll
                for (int j = 0; j < 4; j++) {
                    wmma::mma_sync(c[i][j], ah, bh[j], c[i][j]);
                    wmma::mma_sync(c[i][j], ah, bl[j], c[i][j]);
                    wmma::mma_sync(c[i][j], al, bh[j], c[i][j]);
                }
            }
        }
        __syncthreads();
    }

    #pragma unroll
    for (int i = 0; i < 4; i++) {
        int row = m0 + warp_m * 64 + i * 16;
        #pragma unroll
        for (int j = 0; j < 4; j++) {
            int col = n0 + warp_n * 64 + j * 16;
            wmma::store_matrix_sync(C + (size_t)row * HID + col, c[i][j], HID,
                                    wmma::mem_row_major);
        }
    }
}

// ---------------- pooling ----------------
__global__ void count_kernel(const int* __restrict__ gid, float* __restrict__ cnt) {
    __shared__ int s[N_GRAPHS];
    if (threadIdx.x < N_GRAPHS) s[threadIdx.x] = 0;
    __syncthreads();
    for (int i = threadIdx.x; i < N_NODES; i += blockDim.x)
        atomicAdd(&s[gid[i]], 1);
    __syncthreads();
    if (threadIdx.x < N_GRAPHS) cnt[threadIdx.x] = (float)s[threadIdx.x];
}

#define POOL_CHUNK 160
__global__ void pool_kernel(const float* __restrict__ h, const int* __restrict__ gid,
                            float* __restrict__ pool) {
    __shared__ int sg[POOL_CHUNK];
    int n0 = blockIdx.x * POOL_CHUNK;
    int n1 = min(n0 + POOL_CHUNK, N_NODES);
    for (int i = threadIdx.x; i < n1 - n0; i += blockDim.x) sg[i] = gid[n0 + i];
    __syncthreads();

    int c = threadIdx.x * 4;
    float4 acc = make_float4(0.f, 0.f, 0.f, 0.f);
    int cur = sg[0];
    for (int n = n0; n < n1; n++) {
        int g = sg[n - n0];
        if (g != cur) {
            float* p = pool + cur * HID + c;
            atomicAdd(p + 0, acc.x); atomicAdd(p + 1, acc.y);
            atomicAdd(p + 2, acc.z); atomicAdd(p + 3, acc.w);
            acc = make_float4(0.f, 0.f, 0.f, 0.f);
            cur = g;
        }
        float4 v = *reinterpret_cast<const float4*>(h + n * HID + c);
        acc.x += v.x; acc.y += v.y; acc.z += v.z; acc.w += v.w;
    }
    float* p = pool + cur * HID + c;
    atomicAdd(p + 0, acc.x); atomicAdd(p + 1, acc.y);
    atomicAdd(p + 2, acc.z); atomicAdd(p + 3, acc.w);
}

__global__ void div_kernel(float* __restrict__ pool, const float* __restrict__ cnt) {
    int i = blockIdx.x * blockDim.x + threadIdx.x;
    if (i < N_GRAPHS * HID) {
        float inv = 1.0f / fmaxf(cnt[i / HID], 1.0f);
        pool[i] *= inv;
    }
}

// ---------------- MLP head ----------------
__global__ void dense512(const float* __restrict__ in, const float* __restrict__ W,
                         const float* __restrict__ b, float* __restrict__ out) {
    __shared__ float sh[HID];
    int g = blockIdx.x;
    for (int i = threadIdx.x; i < HID; i += blockDim.x) sh[i] = in[g * HID + i];
    __syncthreads();
    int n = blockIdx.y * 256 + threadIdx.x;
    float acc = b[n];
    #pragma unroll 8
    for (int k = 0; k < HID; k++)
        acc = fmaf(sh[k], W[k * HID + n], acc);
    out[g * HID + n] = fmaxf(acc, 0.0f);
}

__global__ void dense_out(const float* __restrict__ in, const float* __restrict__ W,
                          const float* __restrict__ b, float* __restrict__ out) {
    int g = blockIdx.x;
    int n = threadIdx.x;
    float acc = b[n];
    for (int k = 0; k < HID; k++)
        acc = fmaf(in[g * HID + k], W[k * N_CLASSES + n], acc);
    out[g * N_CLASSES + n] = acc;
}

// ---------------- launch ----------------
extern "C" void kernel_launch(void* const* d_in, const int* in_sizes, int n_in,
                              void* d_out, int out_size) {
    const float* x    = (const float*)d_in[0];
    const int*   src  = (const int*)  d_in[1];
    const int*   dst  = (const int*)  d_in[2];
    const int*   gid  = (const int*)  d_in[3];
    const float* W1   = (const float*)d_in[4];
    const float* b1   = (const float*)d_in[5];
    const float* W2   = (const float*)d_in[6];
    const float* b2   = (const float*)d_in[7];
    const float* W3   = (const float*)d_in[8];
    const float* b3   = (const float*)d_in[9];
    const float* Wc1  = (const float*)d_in[10];
    const float* bc1  = (const float*)d_in[11];
    const float* Wc2  = (const float*)d_in[12];
    const float* bc2  = (const float*)d_in[13];
    const float* Wc3  = (const float*)d_in[14];
    const float* bc3  = (const float*)d_in[15];
    float* out = (float*)d_out;

    float *bufA, *bufB, *doutv, *dinv, *pool, *cnt, *m1, *m2;
    int *cin_, *cout_, *rowoff, *cursor, *csrc;
    __nv_bfloat16 *Ahi, *Alo, *Whi, *Wlo;
    cudaGetSymbolAddress((void**)&bufA,   g_bufA);
    cudaGetSymbolAddress((void**)&bufB,   g_bufB);
    cudaGetSymbolAddress((void**)&doutv,  g_dout);
    cudaGetSymbolAddress((void**)&dinv,   g_din);
    cudaGetSymbolAddress((void**)&pool,   g_pool);
    cudaGetSymbolAddress((void**)&cnt,    g_cnt);
    cudaGetSymbolAddress((void**)&m1,     g_mlp1);
    cudaGetSymbolAddress((void**)&m2,     g_mlp2);
    cudaGetSymbolAddress((void**)&cin_,   g_cin);
    cudaGetSymbolAddress((void**)&cout_,  g_cout);
    cudaGetSymbolAddress((void**)&rowoff, g_rowoff);
    cudaGetSymbolAddress((void**)&cursor, g_cursor);
    cudaGetSymbolAddress((void**)&csrc,   g_csrc);
    cudaGetSymbolAddress((void**)&Ahi,    g_Ahi);
    cudaGetSymbolAddress((void**)&Alo,    g_Alo);
    cudaGetSymbolAddress((void**)&Whi,    g_Whi);
    cudaGetSymbolAddress((void**)&Wlo,    g_Wlo);

    const int smem_gemm = 2 * STAGE_ELEMS * (int)sizeof(__nv_bfloat16);  // 122880
    cudaFuncSetAttribute(gemm_wmma, cudaFuncAttributeMaxDynamicSharedMemorySize, smem_gemm);

    const int nb_nodes = (N_NODES + 255) / 256;
    const int nb_edges = (N_EDGES + 255) / 256;
    dim3 gemm_grid(MROWS / GBM, HID / GBN);   // (157, 2)

    // ---- CSR build + degree normalizers ----
    zero_i2<<<nb_nodes, 256>>>(cin_, cout_, N_NODES);
    deg_kernel<<<nb_edges, 256>>>(src, dst, cout_, cin_);
    scan_kernel<<<1, 1024>>>(cin_, cout_, rowoff, cursor, dinv, doutv);
    bin_kernel<<<nb_edges, 256>>>(src, dst, cursor, csrc);

    // ---- layer 1 ----
    {
        wsplit<<<(IN_DIM * HID + 255) / 256, 256>>>(W1, Whi, Wlo, IN_DIM, HID);
        int t4 = N_NODES * IN_DIM / 4;
        split_scaled<<<(t4 + 255) / 256, 256>>>(x, doutv, Ahi, Alo, t4, IN_DIM);
        gemm_wmma<<<gemm_grid, 256, smem_gemm>>>(Ahi, Alo, Whi, Wlo, bufA, IN_DIM);
        gather_fin<<<N_NODES, 128>>>(bufA, csrc, rowoff, dinv, doutv, b1,
                                     Ahi, Alo, nullptr, 0);
    }
    // ---- layer 2 ----
    {
        wsplit<<<(HID * HID + 255) / 256, 256>>>(W2, Whi, Wlo, HID, HID);
        gemm_wmma<<<gemm_grid, 256, smem_gemm>>>(Ahi, Alo, Whi, Wlo, bufA, HID);
        gather_fin<<<N_NODES, 128>>>(bufA, csrc, rowoff, dinv, doutv, b2,
                                     Ahi, Alo, nullptr, 0);
    }
    // ---- layer 3 ----
    {
        wsplit<<<(HID * HID + 255) / 256, 256>>>(W3, Whi, Wlo, HID, HID);
        gemm_wmma<<<gemm_grid, 256, smem_gemm>>>(Ahi, Alo, Whi, Wlo, bufA, HID);
        gather_fin<<<N_NODES, 128>>>(bufA, csrc, rowoff, dinv, doutv, b3,
                                     nullptr, nullptr, bufB, 1);
    }

    // ---- mean pooling ----
    zero_f<<<(N_GRAPHS * HID + 255) / 256, 256>>>(pool, N_GRAPHS * HID);
    count_kernel<<<1, 256>>>(gid, cnt);
    pool_kernel<<<(N_NODES + POOL_CHUNK - 1) / POOL_CHUNK, 128>>>(bufB, gid, pool);
    div_kernel<<<(N_GRAPHS * HID + 255) / 256, 256>>>(pool, cnt);

    // ---- MLP head ----
    dense512<<<dim3(N_GRAPHS, 2), 256>>>(pool, Wc1, bc1, m1);
    dense512<<<dim3(N_GRAPHS, 2), 256>>>(m1, Wc2, bc2, m2);
    dense_out<<<N_GRAPHS, 16>>>(m2, Wc3, bc3, out);
}